// round 1
// baseline (speedup 1.0000x reference)
#include <cuda_runtime.h>
#include <cstddef>

#define VOCABN 50000
#define DIMN   300
#define HN     100
#define TN     512
#define BN     256
#define OUTN   3
#define G4     400   // 4*H

// ---------------- scratch (static device globals; no allocation) ----------------
__device__ float g_table[(size_t)VOCABN * G4];   // emb @ w_ih0^T + b_ih0 + b_hh0   (80 MB)
__device__ float g_xg[(size_t)BN * TN * G4];     // gate preacts for layers 1,2     (210 MB)
__device__ float g_h[(size_t)BN * TN * HN];      // per-layer hidden outputs        (52 MB)
__device__ float g_hlast[BN * HN];

// ---------------- GEMM: C[m,n] = sum_k A[m,k]*Bm[n,k] + bias1[n] + bias2[n] -----
// 64x64 tile, BK=16, 256 threads, 4x4 per-thread microtile.
// SKIP=1: M = BN*TN rows; skip whole tile if its first timestep >= lengths[b].
template<int SKIP>
__global__ void __launch_bounds__(256)
gemm_tn(const float* __restrict__ A, int M, int K,
        const float* __restrict__ Bm, int N,
        const float* __restrict__ bias1, const float* __restrict__ bias2,
        const int* __restrict__ lengths,
        float* __restrict__ C)
{
    __shared__ float As[16][68];
    __shared__ float Bs[16][68];

    const int m0 = blockIdx.y * 64;
    const int n0 = blockIdx.x * 64;
    if (SKIP) {
        int b  = m0 / TN;
        int t0 = m0 % TN;           // 512 % 64 == 0 -> tile lies within one batch row
        if (t0 >= lengths[b]) return;
    }
    const int tid = threadIdx.x;
    const int tx = tid & 15;
    const int ty = tid >> 4;
    const int lr = tid >> 2;        // 0..63  row within tile
    const int lk = (tid & 3) * 4;   // 0,4,8,12

    float acc[4][4] = {};

    for (int k0 = 0; k0 < K; k0 += 16) {
#pragma unroll
        for (int j = 0; j < 4; j++) {
            int k = k0 + lk + j;
            int m = m0 + lr;
            As[lk + j][lr] = (m < M && k < K) ? A[(size_t)m * K + k] : 0.f;
            int n = n0 + lr;
            Bs[lk + j][lr] = (n < N && k < K) ? Bm[(size_t)n * K + k] : 0.f;
        }
        __syncthreads();
#pragma unroll
        for (int k = 0; k < 16; k++) {
            float4 a4 = *reinterpret_cast<const float4*>(&As[k][ty * 4]);
            float4 b4 = *reinterpret_cast<const float4*>(&Bs[k][tx * 4]);
            float a[4] = {a4.x, a4.y, a4.z, a4.w};
            float bb[4] = {b4.x, b4.y, b4.z, b4.w};
#pragma unroll
            for (int i = 0; i < 4; i++)
#pragma unroll
                for (int jj = 0; jj < 4; jj++)
                    acc[i][jj] += a[i] * bb[jj];
        }
        __syncthreads();
    }
#pragma unroll
    for (int i = 0; i < 4; i++) {
        int m = m0 + ty * 4 + i;
        if (m >= M) continue;
#pragma unroll
        for (int jj = 0; jj < 4; jj++) {
            int n = n0 + tx * 4 + jj;
            if (n < N)
                C[(size_t)m * N + n] = acc[i][jj] + bias1[n] + bias2[n];
        }
    }
}

// ---------------- LSTM scan ----------------
__device__ __forceinline__ float sigm_(float x)  { return 1.f / (1.f + __expf(-x)); }
__device__ __forceinline__ float tanh_(float x)  { return 2.f / (1.f + __expf(-2.f * x)) - 1.f; }

// MODE 0: layer 0 (xg = gather from g_table via token ids), writes h_out
// MODE 1: middle layer (xg buffer),                          writes h_out
// MODE 2: last layer (xg buffer),                            writes hlast only
template<int MODE>
__global__ void __launch_bounds__(400, 1)
lstm_scan(const float* __restrict__ xg,       // table [VOCAB,400] (MODE0) or xg [B*T,400]
          const int* __restrict__ xtok,       // MODE0 only
          const int* __restrict__ lengths,
          const float* __restrict__ w_hh,     // [400,100]
          float* __restrict__ h_out,          // [B,T,100]
          float* __restrict__ hlast)          // [B,100]
{
    const int b = blockIdx.x;
    const int r = threadIdx.x;                 // gate row 0..399
    __shared__ __align__(16) float h_s[100];
    __shared__ float gates_s[400];
    __shared__ int   idx_s[TN];

    const int len = lengths[b];

    if (MODE == 0) {
        for (int t = r; t < TN; t += 400) idx_s[t] = xtok[b * TN + t];
    }

    // per-thread gate weights in registers
    float w[100];
#pragma unroll
    for (int k = 0; k < 100; k++) w[k] = w_hh[r * 100 + k];

    if (r < 100) h_s[r] = 0.f;
    float c = 0.f;
    __syncthreads();

    const float4* h4 = reinterpret_cast<const float4*>(h_s);

    // prefetch xg row for t=0
    float xg_next;
    if (MODE == 0) xg_next = xg[(size_t)idx_s[0] * G4 + r];
    else           xg_next = xg[((size_t)b * TN) * G4 + r];

    for (int t = 0; t < len; t++) {
        float xv = xg_next;
        if (t + 1 < len) {
            if (MODE == 0) xg_next = xg[(size_t)idx_s[t + 1] * G4 + r];
            else           xg_next = xg[((size_t)b * TN + t + 1) * G4 + r];
        }
        float acc = xv;
#pragma unroll
        for (int q = 0; q < 25; q++) {
            float4 hh = h4[q];
            acc += hh.x * w[4 * q + 0];
            acc += hh.y * w[4 * q + 1];
            acc += hh.z * w[4 * q + 2];
            acc += hh.w * w[4 * q + 3];
        }
        gates_s[r] = acc;
        __syncthreads();
        if (r < 100) {
            float ig = sigm_(gates_s[r]);
            float fg = sigm_(gates_s[100 + r]);
            float gg = tanh_(gates_s[200 + r]);
            float og = sigm_(gates_s[300 + r]);
            c = fg * c + ig * gg;
            float hn = og * tanh_(c);
            h_s[r] = hn;
            if (MODE != 2) h_out[((size_t)b * TN + t) * HN + r] = hn;
        }
        __syncthreads();
    }
    if (MODE == 2 && r < 100) hlast[b * HN + r] = h_s[r];
}

// ---------------- head: out[b,o] = hlast[b,:] . w_fc[o,:] + b_fc[o] ----------------
__global__ void head_kernel(const float* __restrict__ hlast,
                            const float* __restrict__ w_fc,
                            const float* __restrict__ b_fc,
                            float* __restrict__ out)
{
    int b = blockIdx.x * blockDim.x + threadIdx.x;
    if (b >= BN) return;
#pragma unroll
    for (int o = 0; o < OUTN; o++) {
        float s = b_fc[o];
#pragma unroll
        for (int k = 0; k < HN; k++)
            s += hlast[b * HN + k] * w_fc[o * HN + k];
        out[b * OUTN + o] = s;
    }
}

// ---------------- launch ----------------
extern "C" void kernel_launch(void* const* d_in, const int* in_sizes, int n_in,
                              void* d_out, int out_size)
{
    const int*   x      = (const int*)d_in[0];
    const int*   lens   = (const int*)d_in[1];
    const float* emb    = (const float*)d_in[2];
    const float* w_ih0  = (const float*)d_in[3];
    const float* w_hh0  = (const float*)d_in[4];
    const float* b_ih0  = (const float*)d_in[5];
    const float* b_hh0  = (const float*)d_in[6];
    const float* w_ih1  = (const float*)d_in[7];
    const float* w_hh1  = (const float*)d_in[8];
    const float* b_ih1  = (const float*)d_in[9];
    const float* b_hh1  = (const float*)d_in[10];
    const float* w_ih2  = (const float*)d_in[11];
    const float* w_hh2  = (const float*)d_in[12];
    const float* b_ih2  = (const float*)d_in[13];
    const float* b_hh2  = (const float*)d_in[14];
    const float* w_fc   = (const float*)d_in[15];
    const float* b_fc   = (const float*)d_in[16];
    float* out = (float*)d_out;

    void *p_table, *p_xg, *p_h, *p_hlast;
    cudaGetSymbolAddress(&p_table, g_table);
    cudaGetSymbolAddress(&p_xg,    g_xg);
    cudaGetSymbolAddress(&p_h,     g_h);
    cudaGetSymbolAddress(&p_hlast, g_hlast);
    float* table = (float*)p_table;
    float* xg    = (float*)p_xg;
    float* h     = (float*)p_h;
    float* hlast = (float*)p_hlast;

    const int M  = BN * TN;
    dim3 blk(256);

    // 1) vocab table GEMM: table = emb @ w_ih0^T + b_ih0 + b_hh0
    {
        dim3 grid((G4 + 63) / 64, (VOCABN + 63) / 64);
        gemm_tn<0><<<grid, blk>>>(emb, VOCABN, DIMN, w_ih0, G4, b_ih0, b_hh0, nullptr, table);
    }
    // 2) layer 0 scan (gathers table rows directly)
    lstm_scan<0><<<BN, 400>>>(table, x, lens, w_hh0, h, nullptr);

    // 3) layer 1 xg GEMM (+length tile-skip), then scan
    {
        dim3 grid((G4 + 63) / 64, M / 64);
        gemm_tn<1><<<grid, blk>>>(h, M, HN, w_ih1, G4, b_ih1, b_hh1, lens, xg);
    }
    lstm_scan<1><<<BN, 400>>>(xg, nullptr, lens, w_hh1, h, nullptr);

    // 4) layer 2 xg GEMM, then scan (hlast only)
    {
        dim3 grid((G4 + 63) / 64, M / 64);
        gemm_tn<1><<<grid, blk>>>(h, M, HN, w_ih2, G4, b_ih2, b_hh2, lens, xg);
    }
    lstm_scan<2><<<BN, 400>>>(xg, nullptr, lens, w_hh2, nullptr, hlast);

    // 5) head
    head_kernel<<<1, 256>>>(hlast, w_fc, b_fc, out);
}

// round 2
// speedup vs baseline: 1.4052x; 1.4052x over previous
#include <cuda_runtime.h>
#include <cstddef>

#define VOCABN 50000
#define DIMN   300
#define HN     100
#define TN     512
#define BN     256
#define OUTN   3
#define G4     400   // 4*H

// ---------------- scratch (static device globals; no allocation) ----------------
__device__ float g_table[(size_t)VOCABN * G4];   // emb @ w_ih0^T + b_ih0 + b_hh0
__device__ float g_xg[(size_t)BN * TN * G4];     // gate preacts for layers 1,2
__device__ float g_h[(size_t)BN * TN * HN];      // per-layer hidden outputs
__device__ float g_hlast[BN * HN];
__device__ int   g_order[BN];                    // batch ids, longest-first

// ---------------- packed f32x2 helpers (Blackwell) ----------------
typedef unsigned long long ull;

__device__ __forceinline__ ull pack2(float x, float y) {
    ull r;
    asm("mov.b64 %0, {%1, %2};" : "=l"(r) : "f"(x), "f"(y));
    return r;
}
__device__ __forceinline__ void unpack2(ull v, float& x, float& y) {
    asm("mov.b64 {%0, %1}, %2;" : "=f"(x), "=f"(y) : "l"(v));
}
__device__ __forceinline__ ull fma2(ull a, ull b, ull c) {
    ull d;
    asm("fma.rn.f32x2 %0, %1, %2, %3;" : "=l"(d) : "l"(a), "l"(b), "l"(c));
    return d;
}

// ---------------- length-descending schedule (rank sort, O(B^2), trivial) -------
__global__ void sort_order(const int* __restrict__ lengths, int* __restrict__ order)
{
    __shared__ int ls[BN];
    int b = threadIdx.x;
    ls[b] = lengths[b];
    __syncthreads();
    int len = ls[b];
    int rank = 0;
#pragma unroll 8
    for (int j = 0; j < BN; j++) {
        int lj = ls[j];
        rank += (lj > len) || (lj == len && j < b);
    }
    order[rank] = b;
}

// ---------------- GEMM: C[m,n] = sum_k A[m,k]*Bm[n,k] + bias1[n] + bias2[n] -----
// 64x64 tile, BK=16, 256 threads, 4x4 per-thread microtile, f32x2 packed FMA.
// SKIP=1: skip whole tile if its first timestep >= lengths[b].
template<int SKIP>
__global__ void __launch_bounds__(256)
gemm_tn(const float* __restrict__ A, int M, int K,
        const float* __restrict__ Bm, int N,
        const float* __restrict__ bias1, const float* __restrict__ bias2,
        const int* __restrict__ lengths,
        float* __restrict__ C)
{
    __shared__ __align__(16) float As[16][68];
    __shared__ __align__(16) float Bs[16][68];

    const int m0 = blockIdx.y * 64;
    const int n0 = blockIdx.x * 64;
    if (SKIP) {
        int b  = m0 / TN;
        int t0 = m0 % TN;           // 512 % 64 == 0 -> tile lies in one batch row
        if (t0 >= lengths[b]) return;
    }
    const int tid = threadIdx.x;
    const int tx = tid & 15;
    const int ty = tid >> 4;
    const int lr = tid >> 2;        // 0..63  row within tile
    const int lk = (tid & 3) * 4;   // 0,4,8,12

    ull acc2[4][2];
#pragma unroll
    for (int i = 0; i < 4; i++) { acc2[i][0] = 0ULL; acc2[i][1] = 0ULL; }

    for (int k0 = 0; k0 < K; k0 += 16) {
#pragma unroll
        for (int j = 0; j < 4; j++) {
            int k = k0 + lk + j;
            int m = m0 + lr;
            As[lk + j][lr] = (m < M && k < K) ? A[(size_t)m * K + k] : 0.f;
            int n = n0 + lr;
            Bs[lk + j][lr] = (n < N && k < K) ? Bm[(size_t)n * K + k] : 0.f;
        }
        __syncthreads();
#pragma unroll
        for (int k = 0; k < 16; k++) {
            float4     a4 = *reinterpret_cast<const float4*>(&As[k][ty * 4]);
            ulonglong2 b2 = *reinterpret_cast<const ulonglong2*>(&Bs[k][tx * 4]);
            ull am;
            am = pack2(a4.x, a4.x);
            acc2[0][0] = fma2(am, b2.x, acc2[0][0]);
            acc2[0][1] = fma2(am, b2.y, acc2[0][1]);
            am = pack2(a4.y, a4.y);
            acc2[1][0] = fma2(am, b2.x, acc2[1][0]);
            acc2[1][1] = fma2(am, b2.y, acc2[1][1]);
            am = pack2(a4.z, a4.z);
            acc2[2][0] = fma2(am, b2.x, acc2[2][0]);
            acc2[2][1] = fma2(am, b2.y, acc2[2][1]);
            am = pack2(a4.w, a4.w);
            acc2[3][0] = fma2(am, b2.x, acc2[3][0]);
            acc2[3][1] = fma2(am, b2.y, acc2[3][1]);
        }
        __syncthreads();
    }
#pragma unroll
    for (int i = 0; i < 4; i++) {
        int m = m0 + ty * 4 + i;
        if (m >= M) continue;
        float c0, c1, c2, c3;
        unpack2(acc2[i][0], c0, c1);
        unpack2(acc2[i][1], c2, c3);
        float cv[4] = {c0, c1, c2, c3};
#pragma unroll
        for (int jj = 0; jj < 4; jj++) {
            int n = n0 + tx * 4 + jj;
            if (n < N)
                C[(size_t)m * N + n] = cv[jj] + bias1[n] + bias2[n];
        }
    }
}

// ---------------- LSTM scan ----------------
__device__ __forceinline__ float sigm_(float x) { return 1.f / (1.f + __expf(-x)); }
__device__ __forceinline__ float tanh_(float x) { return 2.f / (1.f + __expf(-2.f * x)) - 1.f; }

// MODE 0: layer 0 (xg = gather from g_table via token ids), writes h_out
// MODE 1: middle layer (xg buffer),                          writes h_out
// MODE 2: last layer (xg buffer),                            writes hlast only
template<int MODE>
__global__ void __launch_bounds__(400, 1)
lstm_scan(const float* __restrict__ xg,       // table [VOCAB,400] (MODE0) or xg [B*T,400]
          const int* __restrict__ xtok,       // MODE0 only
          const int* __restrict__ lengths,
          const int* __restrict__ order,
          const float* __restrict__ w_hh,     // [400,100]
          float* __restrict__ h_out,          // [B,T,100]
          float* __restrict__ hlast)          // [B,100]
{
    const int b = order[blockIdx.x];           // longest-first schedule
    const int r = threadIdx.x;                 // gate row 0..399
    __shared__ __align__(16) float h_s[100];
    __shared__ float gates_s[400];
    __shared__ int   idx_s[TN];

    const int len = lengths[b];

    if (MODE == 0) {
        for (int t = r; t < TN; t += 400) idx_s[t] = xtok[b * TN + t];
    }

    // per-thread gate weights, packed f32x2 pairs, in registers
    ull w2[50];
    {
        const ull* wrow = reinterpret_cast<const ull*>(w_hh + r * 100); // 400B aligned
#pragma unroll
        for (int j = 0; j < 50; j++) w2[j] = wrow[j];
    }

    if (r < 100) h_s[r] = 0.f;
    float c = 0.f;
    __syncthreads();

    const ulonglong2* h2 = reinterpret_cast<const ulonglong2*>(h_s);

    // gate selector: rows [200,300) use tanh, others sigmoid
    const bool is_t = (r >= 200 && r < 300);

    // prefetch xg row for t=0
    float xg_next;
    if (MODE == 0) xg_next = xg[(size_t)idx_s[0] * G4 + r];
    else           xg_next = xg[((size_t)b * TN) * G4 + r];

    for (int t = 0; t < len; t++) {
        float xv = xg_next;
        if (t + 1 < len) {
            if (MODE == 0) xg_next = xg[(size_t)idx_s[t + 1] * G4 + r];
            else           xg_next = xg[((size_t)b * TN + t + 1) * G4 + r];
        }
        // matvec: 25 LDS.128 + 50 packed f32x2 FMA, 2 independent chains
        ull acc0 = pack2(xv, 0.f);
        ull acc1 = 0ULL;
#pragma unroll
        for (int q = 0; q < 25; q++) {
            ulonglong2 hh = h2[q];
            acc0 = fma2(hh.x, w2[2 * q],     acc0);
            acc1 = fma2(hh.y, w2[2 * q + 1], acc1);
        }
        float a0, a1, a2, a3;
        unpack2(acc0, a0, a1);
        unpack2(acc1, a2, a3);
        float acc = (a0 + a1) + (a2 + a3);

        // activation distributed over all 400 threads (no divergence: selects)
        float z = is_t ? 2.f * acc : acc;
        float s = 1.f / (1.f + __expf(-z));
        gates_s[r] = is_t ? (2.f * s - 1.f) : s;
        __syncthreads();

        if (r < 100) {
            float ig = gates_s[r];
            float fg = gates_s[100 + r];
            float gg = gates_s[200 + r];
            float og = gates_s[300 + r];
            c = fg * c + ig * gg;
            float hn = og * tanh_(c);
            h_s[r] = hn;
            if (MODE != 2) h_out[((size_t)b * TN + t) * HN + r] = hn;
        }
        __syncthreads();
    }
    if (MODE == 2 && r < 100) hlast[b * HN + r] = h_s[r];
}

// ---------------- head ----------------
__global__ void head_kernel(const float* __restrict__ hlast,
                            const float* __restrict__ w_fc,
                            const float* __restrict__ b_fc,
                            float* __restrict__ out)
{
    int b = blockIdx.x * blockDim.x + threadIdx.x;
    if (b >= BN) return;
#pragma unroll
    for (int o = 0; o < OUTN; o++) {
        float s = b_fc[o];
#pragma unroll
        for (int k = 0; k < HN; k++)
            s += hlast[b * HN + k] * w_fc[o * HN + k];
        out[b * OUTN + o] = s;
    }
}

// ---------------- launch ----------------
extern "C" void kernel_launch(void* const* d_in, const int* in_sizes, int n_in,
                              void* d_out, int out_size)
{
    const int*   x      = (const int*)d_in[0];
    const int*   lens   = (const int*)d_in[1];
    const float* emb    = (const float*)d_in[2];
    const float* w_ih0  = (const float*)d_in[3];
    const float* w_hh0  = (const float*)d_in[4];
    const float* b_ih0  = (const float*)d_in[5];
    const float* b_hh0  = (const float*)d_in[6];
    const float* w_ih1  = (const float*)d_in[7];
    const float* w_hh1  = (const float*)d_in[8];
    const float* b_ih1  = (const float*)d_in[9];
    const float* b_hh1  = (const float*)d_in[10];
    const float* w_ih2  = (const float*)d_in[11];
    const float* w_hh2  = (const float*)d_in[12];
    const float* b_ih2  = (const float*)d_in[13];
    const float* b_hh2  = (const float*)d_in[14];
    const float* w_fc   = (const float*)d_in[15];
    const float* b_fc   = (const float*)d_in[16];
    float* out = (float*)d_out;

    void *p_table, *p_xg, *p_h, *p_hlast, *p_order;
    cudaGetSymbolAddress(&p_table, g_table);
    cudaGetSymbolAddress(&p_xg,    g_xg);
    cudaGetSymbolAddress(&p_h,     g_h);
    cudaGetSymbolAddress(&p_hlast, g_hlast);
    cudaGetSymbolAddress(&p_order, g_order);
    float* table = (float*)p_table;
    float* xg    = (float*)p_xg;
    float* h     = (float*)p_h;
    float* hlast = (float*)p_hlast;
    int*   order = (int*)p_order;

    const int M = BN * TN;
    dim3 blk(256);

    // 0) longest-first schedule for the scans
    sort_order<<<1, BN>>>(lens, order);

    // 1) vocab table GEMM: table = emb @ w_ih0^T + b_ih0 + b_hh0
    {
        dim3 grid((G4 + 63) / 64, (VOCABN + 63) / 64);
        gemm_tn<0><<<grid, blk>>>(emb, VOCABN, DIMN, w_ih0, G4, b_ih0, b_hh0, nullptr, table);
    }
    // 2) layer 0 scan (gathers table rows directly)
    lstm_scan<0><<<BN, 400>>>(table, x, lens, order, w_hh0, h, nullptr);

    // 3) layer 1 xg GEMM (+length tile-skip), then scan
    {
        dim3 grid((G4 + 63) / 64, M / 64);
        gemm_tn<1><<<grid, blk>>>(h, M, HN, w_ih1, G4, b_ih1, b_hh1, lens, xg);
    }
    lstm_scan<1><<<BN, 400>>>(xg, nullptr, lens, order, w_hh1, h, nullptr);

    // 4) layer 2 xg GEMM, then scan (hlast only)
    {
        dim3 grid((G4 + 63) / 64, M / 64);
        gemm_tn<1><<<grid, blk>>>(h, M, HN, w_ih2, G4, b_ih2, b_hh2, lens, xg);
    }
    lstm_scan<2><<<BN, 400>>>(xg, nullptr, lens, order, w_hh2, nullptr, hlast);

    // 5) head
    head_kernel<<<1, 256>>>(hlast, w_fc, b_fc, out);
}

// round 3
// speedup vs baseline: 1.5186x; 1.0807x over previous
#include <cuda_runtime.h>
#include <cstddef>

#define VOCABN 50000
#define DIMN   300
#define HN     100
#define TN     512
#define BN     256
#define OUTN   3
#define G4     400   // 4*H

// ---------------- scratch (static device globals; no allocation) ----------------
__device__ float g_table[(size_t)VOCABN * G4];   // emb @ w_ih0^T + b_ih0 + b_hh0
__device__ float g_xg[(size_t)BN * TN * G4];     // gate preacts for layers 1,2
__device__ float g_h[(size_t)BN * TN * HN];      // per-layer hidden outputs
__device__ float g_hlast[BN * HN];
__device__ int   g_order[BN];                    // batch ids, longest-first

// ---------------- packed f32x2 helpers (Blackwell) ----------------
typedef unsigned long long ull;

__device__ __forceinline__ ull pack2(float x, float y) {
    ull r;
    asm("mov.b64 %0, {%1, %2};" : "=l"(r) : "f"(x), "f"(y));
    return r;
}
__device__ __forceinline__ void unpack2(ull v, float& x, float& y) {
    asm("mov.b64 {%0, %1}, %2;" : "=f"(x), "=f"(y) : "l"(v));
}
__device__ __forceinline__ ull fma2(ull a, ull b, ull c) {
    ull d;
    asm("fma.rn.f32x2 %0, %1, %2, %3;" : "=l"(d) : "l"(a), "l"(b), "l"(c));
    return d;
}

// ---------------- length-descending schedule ----------------
__global__ void sort_order(const int* __restrict__ lengths, int* __restrict__ order)
{
    __shared__ int ls[BN];
    int b = threadIdx.x;
    ls[b] = lengths[b];
    __syncthreads();
    int len = ls[b];
    int rank = 0;
#pragma unroll 8
    for (int j = 0; j < BN; j++) {
        int lj = ls[j];
        rank += (lj > len) || (lj == len && j < b);
    }
    order[rank] = b;
}

// ---------------- GEMM: C[m,n] = sum_k A[m,k]*Bm[n,k] + bias1[n] + bias2[n] -----
// 128x64 tile, BK=16, 128 threads, 8x8 per-thread microtile, f32x2 packed FMA.
// SKIP=1: skip whole tile if its first timestep >= lengths[b] (tiles of 128 rows).
template<int SKIP>
__global__ void __launch_bounds__(128)
gemm_tn(const float* __restrict__ A, int M, int K,
        const float* __restrict__ Bm, int N,
        const float* __restrict__ bias1, const float* __restrict__ bias2,
        const int* __restrict__ lengths,
        float* __restrict__ C)
{
    __shared__ __align__(16) float As[16][132];
    __shared__ __align__(16) float Bs[16][68];

    const int m0 = blockIdx.y * 128;
    const int n0 = blockIdx.x * 64;
    if (SKIP) {
        int b  = m0 / TN;
        int t0 = m0 % TN;           // 512 % 128 == 0 -> tile lies in one batch row
        if (t0 >= lengths[b]) return;
    }
    const int tid = threadIdx.x;
    const int tx = tid & 7;         // 0..7  (N, 8 cols each)
    const int ty = tid >> 3;        // 0..15 (M, 8 rows each)

    ull acc[8][4];
#pragma unroll
    for (int i = 0; i < 8; i++)
#pragma unroll
        for (int j = 0; j < 4; j++) acc[i][j] = 0ULL;

    for (int k0 = 0; k0 < K; k0 += 16) {
        // ---- load A tile (128x16) : 512 float4 / 128 threads = 4 each ----
#pragma unroll
        for (int i = 0; i < 4; i++) {
            int f   = i * 128 + tid;      // 0..511
            int row = f >> 2;             // 0..127
            int kq  = (f & 3) * 4;        // 0,4,8,12
            int m   = m0 + row;
            float4 v = make_float4(0.f, 0.f, 0.f, 0.f);
            if (m < M) {
                if (k0 + kq + 3 < K) {
                    v = *reinterpret_cast<const float4*>(&A[(size_t)m * K + k0 + kq]);
                } else {
                    float t0v = (k0 + kq + 0 < K) ? A[(size_t)m * K + k0 + kq + 0] : 0.f;
                    float t1v = (k0 + kq + 1 < K) ? A[(size_t)m * K + k0 + kq + 1] : 0.f;
                    float t2v = (k0 + kq + 2 < K) ? A[(size_t)m * K + k0 + kq + 2] : 0.f;
                    float t3v = (k0 + kq + 3 < K) ? A[(size_t)m * K + k0 + kq + 3] : 0.f;
                    v = make_float4(t0v, t1v, t2v, t3v);
                }
            }
            As[kq + 0][row] = v.x; As[kq + 1][row] = v.y;
            As[kq + 2][row] = v.z; As[kq + 3][row] = v.w;
        }
        // ---- load B tile (64x16) : 256 float4 / 128 threads = 2 each ----
#pragma unroll
        for (int i = 0; i < 2; i++) {
            int f   = i * 128 + tid;      // 0..255
            int row = f >> 2;             // 0..63
            int kq  = (f & 3) * 4;
            int n   = n0 + row;
            float4 v = make_float4(0.f, 0.f, 0.f, 0.f);
            if (n < N) {
                if (k0 + kq + 3 < K) {
                    v = *reinterpret_cast<const float4*>(&Bm[(size_t)n * K + k0 + kq]);
                } else {
                    float t0v = (k0 + kq + 0 < K) ? Bm[(size_t)n * K + k0 + kq + 0] : 0.f;
                    float t1v = (k0 + kq + 1 < K) ? Bm[(size_t)n * K + k0 + kq + 1] : 0.f;
                    float t2v = (k0 + kq + 2 < K) ? Bm[(size_t)n * K + k0 + kq + 2] : 0.f;
                    float t3v = (k0 + kq + 3 < K) ? Bm[(size_t)n * K + k0 + kq + 3] : 0.f;
                    v = make_float4(t0v, t1v, t2v, t3v);
                }
            }
            Bs[kq + 0][row] = v.x; Bs[kq + 1][row] = v.y;
            Bs[kq + 2][row] = v.z; Bs[kq + 3][row] = v.w;
        }
        __syncthreads();
#pragma unroll
        for (int k = 0; k < 16; k++) {
            float4 a0 = *reinterpret_cast<const float4*>(&As[k][ty * 8]);
            float4 a1 = *reinterpret_cast<const float4*>(&As[k][ty * 8 + 4]);
            ulonglong2 b0 = *reinterpret_cast<const ulonglong2*>(&Bs[k][tx * 8]);
            ulonglong2 b1 = *reinterpret_cast<const ulonglong2*>(&Bs[k][tx * 8 + 4]);
            float am[8] = {a0.x, a0.y, a0.z, a0.w, a1.x, a1.y, a1.z, a1.w};
#pragma unroll
            for (int i = 0; i < 8; i++) {
                ull ai = pack2(am[i], am[i]);
                acc[i][0] = fma2(ai, b0.x, acc[i][0]);
                acc[i][1] = fma2(ai, b0.y, acc[i][1]);
                acc[i][2] = fma2(ai, b1.x, acc[i][2]);
                acc[i][3] = fma2(ai, b1.y, acc[i][3]);
            }
        }
        __syncthreads();
    }
#pragma unroll
    for (int i = 0; i < 8; i++) {
        int m = m0 + ty * 8 + i;
        if (m >= M) continue;
        float cv[8];
        unpack2(acc[i][0], cv[0], cv[1]);
        unpack2(acc[i][1], cv[2], cv[3]);
        unpack2(acc[i][2], cv[4], cv[5]);
        unpack2(acc[i][3], cv[6], cv[7]);
#pragma unroll
        for (int j = 0; j < 8; j++) {
            int n = n0 + tx * 8 + j;
            if (n < N)
                C[(size_t)m * N + n] = cv[j] + bias1[n] + bias2[n];
        }
    }
}

// ---------------- LSTM scan (quad-per-hidden-unit layout) ----------------
__device__ __forceinline__ float tanh_(float x) { return 2.f / (1.f + __expf(-2.f * x)) - 1.f; }

// thread tid = j*4 + g : hidden unit j (0..99), gate g (0=i,1=f,2=g,3=o)
// gate row in w_hh / xg: r = g*100 + j
// MODE 0: layer 0 (gather from table via tokens), writes h_out
// MODE 1: middle layer (xg buffer),               writes h_out
// MODE 2: last layer (xg buffer),                 writes hlast only
template<int MODE>
__global__ void __launch_bounds__(400, 1)
lstm_scan(const float* __restrict__ xg,
          const int* __restrict__ xtok,
          const int* __restrict__ lengths,
          const int* __restrict__ order,
          const float* __restrict__ w_hh,     // [400,100]
          float* __restrict__ h_out,          // [B,T,100]
          float* __restrict__ hlast)          // [B,100]
{
    const int b   = order[blockIdx.x];
    const int tid = threadIdx.x;
    const int j   = tid >> 2;                  // hidden unit
    const int g   = tid & 3;                   // gate
    const int r   = g * 100 + j;               // gate row

    __shared__ __align__(16) float h_s[2][104];   // ping-pong hidden state
    __shared__ int idx_s[TN];

    const int len = lengths[b];

    if (MODE == 0) {
        for (int t = tid; t < TN; t += 400) idx_s[t] = xtok[b * TN + t];
    }

    // per-thread gate weights, packed f32x2 pairs, in registers
    ull w2[50];
    {
        const ull* wrow = reinterpret_cast<const ull*>(w_hh + r * 100);
#pragma unroll
        for (int q = 0; q < 50; q++) w2[q] = wrow[q];
    }

    if (tid < 100) h_s[0][tid] = 0.f;
    float c = 0.f;
    __syncthreads();

    const bool is_t = (g == 2);
    const bool gsel = (g & 2) != 0;

    // prefetch xg row for t=0
    float xg_next;
    if (MODE == 0) xg_next = xg[(size_t)idx_s[0] * G4 + r];
    else           xg_next = xg[((size_t)b * TN) * G4 + r];

    for (int t = 0; t < len; t++) {
        float xv = xg_next;
        if (t + 1 < len) {
            if (MODE == 0) xg_next = xg[(size_t)idx_s[t + 1] * G4 + r];
            else           xg_next = xg[((size_t)b * TN + t + 1) * G4 + r];
        }
        const ulonglong2* h2 = reinterpret_cast<const ulonglong2*>(h_s[t & 1]);

        // matvec: 25 LDS.128 (broadcast) + 50 packed f32x2 FMA, 2 chains
        ull acc0 = pack2(xv, 0.f);
        ull acc1 = 0ULL;
#pragma unroll
        for (int q = 0; q < 25; q++) {
            ulonglong2 hh = h2[q];
            acc0 = fma2(hh.x, w2[2 * q],     acc0);
            acc1 = fma2(hh.y, w2[2 * q + 1], acc1);
        }
        float a0, a1, a2, a3;
        unpack2(acc0, a0, a1);
        unpack2(acc1, a2, a3);
        float acc = (a0 + a1) + (a2 + a3);

        // activation (sigmoid for g=0,1,3; tanh for g=2), divergence-free
        float z = is_t ? 2.f * acc : acc;
        float s = 1.f / (1.f + __expf(-z));
        float gate = is_t ? (2.f * s - 1.f) : s;

        // quad exchange via shuffles: collect i,f,g,o in every lane of the quad
        float v1 = __shfl_xor_sync(0xFFFFFFFFu, gate, 1);   // gate of g^1
        float pa = (g & 1) ? v1 : gate;    // even-row gate of this pair (i or g)
        float pb = (g & 1) ? gate : v1;    // odd-row gate of this pair  (f or o)
        float qa = __shfl_xor_sync(0xFFFFFFFFu, pa, 2);     // other pair's even
        float qb = __shfl_xor_sync(0xFFFFFFFFu, pb, 2);     // other pair's odd
        float ig = gsel ? qa : pa;
        float gg = gsel ? pa : qa;
        float fg = gsel ? qb : pb;
        float og = gsel ? pb : qb;

        // cell update (kept redundantly in all 4 lanes of the quad)
        c = fg * c + ig * gg;
        float hn = og * tanh_(c);
        if (g == 0) {
            h_s[(t + 1) & 1][j] = hn;
            if (MODE != 2) h_out[((size_t)b * TN + t) * HN + j] = hn;
        }
        if (MODE == 2 && g == 0 && t == len - 1) hlast[b * HN + j] = hn;
        __syncthreads();
    }
}

// ---------------- head ----------------
__global__ void head_kernel(const float* __restrict__ hlast,
                            const float* __restrict__ w_fc,
                            const float* __restrict__ b_fc,
                            float* __restrict__ out)
{
    int b = blockIdx.x * blockDim.x + threadIdx.x;
    if (b >= BN) return;
#pragma unroll
    for (int o = 0; o < OUTN; o++) {
        float s = b_fc[o];
#pragma unroll
        for (int k = 0; k < HN; k++)
            s += hlast[b * HN + k] * w_fc[o * HN + k];
        out[b * OUTN + o] = s;
    }
}

// ---------------- launch ----------------
extern "C" void kernel_launch(void* const* d_in, const int* in_sizes, int n_in,
                              void* d_out, int out_size)
{
    const int*   x      = (const int*)d_in[0];
    const int*   lens   = (const int*)d_in[1];
    const float* emb    = (const float*)d_in[2];
    const float* w_ih0  = (const float*)d_in[3];
    const float* w_hh0  = (const float*)d_in[4];
    const float* b_ih0  = (const float*)d_in[5];
    const float* b_hh0  = (const float*)d_in[6];
    const float* w_ih1  = (const float*)d_in[7];
    const float* w_hh1  = (const float*)d_in[8];
    const float* b_ih1  = (const float*)d_in[9];
    const float* b_hh1  = (const float*)d_in[10];
    const float* w_ih2  = (const float*)d_in[11];
    const float* w_hh2  = (const float*)d_in[12];
    const float* b_ih2  = (const float*)d_in[13];
    const float* b_hh2  = (const float*)d_in[14];
    const float* w_fc   = (const float*)d_in[15];
    const float* b_fc   = (const float*)d_in[16];
    float* out = (float*)d_out;

    void *p_table, *p_xg, *p_h, *p_hlast, *p_order;
    cudaGetSymbolAddress(&p_table, g_table);
    cudaGetSymbolAddress(&p_xg,    g_xg);
    cudaGetSymbolAddress(&p_h,     g_h);
    cudaGetSymbolAddress(&p_hlast, g_hlast);
    cudaGetSymbolAddress(&p_order, g_order);
    float* table = (float*)p_table;
    float* xg    = (float*)p_xg;
    float* h     = (float*)p_h;
    float* hlast = (float*)p_hlast;
    int*   order = (int*)p_order;

    const int M = BN * TN;
    dim3 blk(128);

    // 0) longest-first schedule for the scans
    sort_order<<<1, BN>>>(lens, order);

    // 1) vocab table GEMM: table = emb @ w_ih0^T + b_ih0 + b_hh0
    {
        dim3 grid((G4 + 63) / 64, (VOCABN + 127) / 128);
        gemm_tn<0><<<grid, blk>>>(emb, VOCABN, DIMN, w_ih0, G4, b_ih0, b_hh0, nullptr, table);
    }
    // 2) layer 0 scan (gathers table rows directly)
    lstm_scan<0><<<BN, 400>>>(table, x, lens, order, w_hh0, h, nullptr);

    // 3) layer 1 xg GEMM (+length tile-skip), then scan
    {
        dim3 grid((G4 + 63) / 64, M / 128);
        gemm_tn<1><<<grid, blk>>>(h, M, HN, w_ih1, G4, b_ih1, b_hh1, lens, xg);
    }
    lstm_scan<1><<<BN, 400>>>(xg, nullptr, lens, order, w_hh1, h, nullptr);

    // 4) layer 2 xg GEMM, then scan (hlast only)
    {
        dim3 grid((G4 + 63) / 64, M / 128);
        gemm_tn<1><<<grid, blk>>>(h, M, HN, w_ih2, G4, b_ih2, b_hh2, lens, xg);
    }
    lstm_scan<2><<<BN, 400>>>(xg, nullptr, lens, order, w_hh2, nullptr, hlast);

    // 5) head
    head_kernel<<<1, 256>>>(hlast, w_fc, b_fc, out);
}